// round 15
// baseline (speedup 1.0000x reference)
#include <cuda_runtime.h>
#include <cuda_bf16.h>
#include <cstdint>

// Shapes (fixed): B=2048, V=256, T=11, K=8, N=8, H=255, K*H=2040
// x_unfolded: (B, V, T, K) fp32 exact one-hot along V (184.5 MB)
// out: (B, 2, T) fp32
//
// Collapse: out[b,o,t] = out_b[o] + sum_k LUT[o][k][ids[b,t,k]]
//
// Fused kernel, one block per slab:
//   Phase A (blocks 0..127): build 16KB LUT, bump d_count.
//   Phase B (all): stream own 88KB slab via a DEPTH-4 ROLLING register
//     pipeline (load slot g&3 for iter g+4 issued before consuming iter g)
//     at launch_bounds(256,6) -> 42-reg budget so ptxas keeps the pipeline.
//     Nonzeros (exactly 88) stashed to smem (LUT not needed yet).
//   Phase C: poll d_count (long done), apply LUT, write out.
//   Last block resets counters (graph-replay determinism).

#define VV 256
#define TT 11
#define KK 8
#define NN 8
#define HH 255
#define KH 2040
#define BB 2048
#define SLAB4 5632        // float4 per slab
#define LUTB 128

__device__ float d_LUT[2 * KK * VV];   // 16 KB
__device__ int   d_count = 0;
__device__ int   d_done  = 0;

__global__ void __launch_bounds__(256, 6) fused_kernel(
    const float4* __restrict__ x,    // (B, V, T, K)
    const float*  __restrict__ sw,   // (N, V, K)
    const float*  __restrict__ hw,   // (K*H, N)
    const float*  __restrict__ ow,   // (2, K*H)
    const float*  __restrict__ ob,   // (2,)
    float*        __restrict__ out)  // (B, 2, T)
{
    __shared__ int   s_cnt;
    __shared__ int   s_key[128];
    __shared__ float s_val[128];
    __shared__ float acc[2][TT];

    const int tid  = threadIdx.x;
    const int bid  = blockIdx.x;
    const int lane = tid & 31;
    const int wid  = tid >> 5;

    if (tid == 0) s_cnt = 0;
    if (tid < 2 * TT) acc[tid / TT][tid % TT] = 0.0f;
    __syncthreads();

    // ------------------------------------------------------------------
    // Phase A (blocks 0..127): build LUT. 8 warps x 2 (k,v) pairs.
    // ------------------------------------------------------------------
    if (bid < LUTB) {
#pragma unroll
        for (int pp = 0; pp < 2; pp++) {
            int p = bid * 16 + wid * 2 + pp;   // 0..2047
            int k = p >> 8, v = p & 255;
            float s[NN];
#pragma unroll
            for (int n = 0; n < NN; n++)
                s[n] = fmaxf(sw[n * (VV * KK) + v * KK + k], 0.0f);
            float a0 = 0.0f, a1 = 0.0f;
            for (int h = lane; h < HH; h += 32) {
                int c = k * HH + h;
                const float4* hr = (const float4*)(hw + c * NN);
                float4 h0 = hr[0], h1 = hr[1];
                float t = h0.x*s[0] + h0.y*s[1] + h0.z*s[2] + h0.w*s[3]
                        + h1.x*s[4] + h1.y*s[5] + h1.z*s[6] + h1.w*s[7];
                t = fmaxf(t, 0.0f);
                a0 += ow[c] * t;
                a1 += ow[KH + c] * t;
            }
#pragma unroll
            for (int o = 16; o; o >>= 1) {
                a0 += __shfl_xor_sync(0xffffffffu, a0, o);
                a1 += __shfl_xor_sync(0xffffffffu, a1, o);
            }
            if (lane == 0) {
                d_LUT[k * VV + v]           = a0;
                d_LUT[KK * VV + k * VV + v] = a1;
            }
        }
        __syncthreads();
        if (tid == 0) { __threadfence(); atomicAdd(&d_count, 1); }
    }

    // ------------------------------------------------------------------
    // Phase B: depth-4 rolling load pipeline over 22 float4 per thread.
    // The refill for iter g+4 issues BEFORE iter g's consume, so ~4 loads
    // stay in flight per thread continuously.
    // ------------------------------------------------------------------
    const float4* xb = x + (size_t)bid * SLAB4 + tid;

    float4 q[4];
#pragma unroll
    for (int j = 0; j < 4; j++)
        q[j] = xb[j * 256];

#pragma unroll
    for (int g = 0; g < 22; g++) {
        float4 cur = q[g & 3];
        if (g + 4 < 22)
            q[g & 3] = xb[(g + 4) * 256];
        if (cur.x != 0.0f || cur.y != 0.0f ||
            cur.z != 0.0f || cur.w != 0.0f) {
            int r = (tid + g * 256) * 4;
            float v4[4] = {cur.x, cur.y, cur.z, cur.w};
#pragma unroll
            for (int qq = 0; qq < 4; qq++) {
                if (v4[qq] != 0.0f) {
                    int pos = atomicAdd(&s_cnt, 1);
                    if (pos < 128) { s_key[pos] = r + qq; s_val[pos] = v4[qq]; }
                }
            }
        }
    }
    __syncthreads();

    // ------------------------------------------------------------------
    // Phase C: wait for LUT (done long ago), then apply.
    // ------------------------------------------------------------------
    if (tid == 0) {
        while (*(volatile int*)&d_count < LUTB) { }
    }
    __syncthreads();
    __threadfence();   // acquire

    int n = min(s_cnt, 128);
    for (int i = tid; i < n; i += 256) {
        int   e   = s_key[i];
        float val = s_val[i];
        int v  = e / (TT * KK);
        int rr = e - v * (TT * KK);
        int t  = rr >> 3;
        int k  = rr & 7;
        atomicAdd(&acc[0][t], val * d_LUT[k * VV + v]);
        atomicAdd(&acc[1][t], val * d_LUT[KK * VV + k * VV + v]);
    }
    __syncthreads();

    if (tid < 2 * TT) {
        int o = tid / TT, t = tid % TT;
        out[((size_t)bid * 2 + o) * TT + t] = acc[o][t] + ob[o];
    }

    // ------------------------------------------------------------------
    // Reset counters (last block out) for graph-replay determinism.
    // ------------------------------------------------------------------
    __syncthreads();
    if (tid == 0) {
        __threadfence();
        if (atomicAdd(&d_done, 1) == BB - 1) {
            d_count = 0;
            d_done  = 0;
            __threadfence();
        }
    }
}

extern "C" void kernel_launch(void* const* d_in, const int* in_sizes, int n_in,
                              void* d_out, int out_size)
{
    const float* x  = (const float*)d_in[0];  // (B, V, T, K)
    const float* sw = (const float*)d_in[1];  // (N, V, K)
    const float* hw = (const float*)d_in[2];  // (K*H, N)
    const float* ow = (const float*)d_in[3];  // (2, K*H)
    const float* ob = (const float*)d_in[4];  // (2,)
    float* out = (float*)d_out;               // (B, 2, T)
    (void)in_sizes; (void)n_in; (void)out_size;

    fused_kernel<<<BB, 256>>>((const float4*)x, sw, hw, ow, ob, out);
}

// round 16
// speedup vs baseline: 1.1972x; 1.1972x over previous
#include <cuda_runtime.h>
#include <cuda_bf16.h>
#include <cstdint>

// Shapes (fixed): B=2048, V=256, T=11, K=8, N=8, H=255, K*H=2040
// x_unfolded: (B, V, T, K) fp32 exact one-hot along V (184.5 MB)
// out: (B, 2, T) fp32
//
// Collapse: out[b,o,t] = out_b[o] + sum_k LUT[o][k][ids[b,t,k]]
//
// Fused kernel, one block per slab:
//   Phase A (blocks 0..127): build 16KB LUT, bump d_count.
//   Phase B (all): R2's plain sequential streaming loop (measured-best
//     DRAM% shape: 60.6%), stash the exactly-88 nonzeros to smem.
//   Phase C: poll d_count (long done by now), apply LUT, write out.
//   Last block resets counters (graph-replay determinism).

#define VV 256
#define TT 11
#define KK 8
#define NN 8
#define HH 255
#define KH 2040
#define BB 2048
#define SLAB4 5632        // float4 per slab
#define LUTB 128

__device__ float d_LUT[2 * KK * VV];   // 16 KB
__device__ int   d_count = 0;
__device__ int   d_done  = 0;

__global__ void __launch_bounds__(256, 8) fused_kernel(
    const float4* __restrict__ x,    // (B, V, T, K)
    const float*  __restrict__ sw,   // (N, V, K)
    const float*  __restrict__ hw,   // (K*H, N)
    const float*  __restrict__ ow,   // (2, K*H)
    const float*  __restrict__ ob,   // (2,)
    float*        __restrict__ out)  // (B, 2, T)
{
    __shared__ int   s_cnt;
    __shared__ int   s_key[128];
    __shared__ float s_val[128];
    __shared__ float acc[2][TT];

    const int tid  = threadIdx.x;
    const int bid  = blockIdx.x;
    const int lane = tid & 31;
    const int wid  = tid >> 5;

    if (tid == 0) s_cnt = 0;
    if (tid < 2 * TT) acc[tid / TT][tid % TT] = 0.0f;
    __syncthreads();

    // ------------------------------------------------------------------
    // Phase A (blocks 0..127): build LUT. 8 warps x 2 (k,v) pairs.
    // ------------------------------------------------------------------
    if (bid < LUTB) {
#pragma unroll
        for (int pp = 0; pp < 2; pp++) {
            int p = bid * 16 + wid * 2 + pp;   // 0..2047
            int k = p >> 8, v = p & 255;
            float s[NN];
#pragma unroll
            for (int n = 0; n < NN; n++)
                s[n] = fmaxf(sw[n * (VV * KK) + v * KK + k], 0.0f);
            float a0 = 0.0f, a1 = 0.0f;
            for (int h = lane; h < HH; h += 32) {
                int c = k * HH + h;
                const float4* hr = (const float4*)(hw + c * NN);
                float4 h0 = hr[0], h1 = hr[1];
                float t = h0.x*s[0] + h0.y*s[1] + h0.z*s[2] + h0.w*s[3]
                        + h1.x*s[4] + h1.y*s[5] + h1.z*s[6] + h1.w*s[7];
                t = fmaxf(t, 0.0f);
                a0 += ow[c] * t;
                a1 += ow[KH + c] * t;
            }
#pragma unroll
            for (int o = 16; o; o >>= 1) {
                a0 += __shfl_xor_sync(0xffffffffu, a0, o);
                a1 += __shfl_xor_sync(0xffffffffu, a1, o);
            }
            if (lane == 0) {
                d_LUT[k * VV + v]           = a0;
                d_LUT[KK * VV + k * VV + v] = a1;
            }
        }
        __syncthreads();
        if (tid == 0) { __threadfence(); atomicAdd(&d_count, 1); }
    }

    // ------------------------------------------------------------------
    // Phase B: R2's measured-best sequential streaming loop.
    // 22 float4 per thread, load -> test -> (rare) stash.
    // ------------------------------------------------------------------
    const float4* xb = x + (size_t)bid * SLAB4;

#pragma unroll
    for (int j = 0; j < 22; j++) {
        int i4 = tid + j * 256;
        float4 q = xb[i4];
        if (q.x != 0.0f || q.y != 0.0f || q.z != 0.0f || q.w != 0.0f) {
            int r = i4 * 4;
            float v4[4] = {q.x, q.y, q.z, q.w};
#pragma unroll
            for (int qq = 0; qq < 4; qq++) {
                if (v4[qq] != 0.0f) {
                    int pos = atomicAdd(&s_cnt, 1);
                    if (pos < 128) { s_key[pos] = r + qq; s_val[pos] = v4[qq]; }
                }
            }
        }
    }
    __syncthreads();

    // ------------------------------------------------------------------
    // Phase C: wait for LUT (done long ago), then apply.
    // ------------------------------------------------------------------
    if (tid == 0) {
        while (*(volatile int*)&d_count < LUTB) { }
    }
    __syncthreads();
    __threadfence();   // acquire

    int n = min(s_cnt, 128);
    for (int i = tid; i < n; i += 256) {
        int   e   = s_key[i];
        float val = s_val[i];
        int v  = e / (TT * KK);
        int rr = e - v * (TT * KK);
        int t  = rr >> 3;
        int k  = rr & 7;
        atomicAdd(&acc[0][t], val * d_LUT[k * VV + v]);
        atomicAdd(&acc[1][t], val * d_LUT[KK * VV + k * VV + v]);
    }
    __syncthreads();

    if (tid < 2 * TT) {
        int o = tid / TT, t = tid % TT;
        out[((size_t)bid * 2 + o) * TT + t] = acc[o][t] + ob[o];
    }

    // ------------------------------------------------------------------
    // Reset counters (last block out) for graph-replay determinism.
    // ------------------------------------------------------------------
    __syncthreads();
    if (tid == 0) {
        __threadfence();
        if (atomicAdd(&d_done, 1) == BB - 1) {
            d_count = 0;
            d_done  = 0;
            __threadfence();
        }
    }
}

extern "C" void kernel_launch(void* const* d_in, const int* in_sizes, int n_in,
                              void* d_out, int out_size)
{
    const float* x  = (const float*)d_in[0];  // (B, V, T, K)
    const float* sw = (const float*)d_in[1];  // (N, V, K)
    const float* hw = (const float*)d_in[2];  // (K*H, N)
    const float* ow = (const float*)d_in[3];  // (2, K*H)
    const float* ob = (const float*)d_in[4];  // (2,)
    float* out = (float*)d_out;               // (B, 2, T)
    (void)in_sizes; (void)n_in; (void)out_size;

    fused_kernel<<<BB, 256>>>((const float4*)x, sw, hw, ow, ob, out);
}